// round 12
// baseline (speedup 1.0000x reference)
#include <cuda_runtime.h>

#define D_    128
#define ED_   16
#define N_MAX 100000
#define L_MAX 5

// per-layer per-node projections, layout [layer][node][16]
__device__ __align__(128) float g_p[(size_t)L_MAX * N_MAX * ED_];
__device__ __align__(128) float g_q[(size_t)L_MAX * N_MAX * ED_];

// edge-MLP weights packed as float pairs for fma.rn.f32x2
__constant__ __align__(16) ulonglong2 cWC[L_MAX][64];
__constant__ __align__(16) ulonglong2 cW2[L_MAX][64];
__constant__ __align__(16) unsigned long long cB1[L_MAX][8];
__constant__ __align__(16) unsigned long long cB2[L_MAX][8];

// ---- f32x2 packed helpers ----
__device__ __forceinline__ unsigned long long pk2(float a) {
    unsigned long long r; asm("mov.b64 %0, {%1, %1};" : "=l"(r) : "f"(a)); return r;
}
__device__ __forceinline__ float2 up2(unsigned long long v) {
    float2 r; asm("mov.b64 {%0, %1}, %2;" : "=f"(r.x), "=f"(r.y) : "l"(v)); return r;
}
__device__ __forceinline__ unsigned long long fma2(unsigned long long a,
                                                   unsigned long long b,
                                                   unsigned long long c) {
    unsigned long long d;
    asm("fma.rn.f32x2 %0, %1, %2, %3;" : "=l"(d) : "l"(a), "l"(b), "l"(c));
    return d;
}
__device__ __forceinline__ unsigned long long add2(unsigned long long a,
                                                   unsigned long long b) {
    unsigned long long d;
    asm("add.rn.f32x2 %0, %1, %2;" : "=l"(d) : "l"(a), "l"(b));
    return d;
}

// ---------------------------------------------------------------------------
// All L layers of LayerNorm + both 128->16 projections. 8 rows per warp,
// rows live in registers across layers. Split-K projection (R11 proven).
// ---------------------------------------------------------------------------
#define LNW 16   // warps per block
__global__ __launch_bounds__(512) void ln_all_kernel(
    const float* __restrict__ s_in, float* __restrict__ s_out,
    const float* __restrict__ lnw, const float* __restrict__ lnb,
    const float* __restrict__ eW1 /* [L,272,16] */, int n, int L)
{
    extern __shared__ __align__(16) float sm[];
    float* wT     = sm;                       // [5][32*132] transposed Wa|Wb
    float* sLn    = wT + L_MAX * 4224;        // [5][256] lnw|lnb
    float* rowbuf = sLn + L_MAX * 256;        // [LNW warps][8*132]

    for (int l = 0; l < L; ++l) {
        const float* w1 = eW1 + (size_t)l * 272 * 16;
        float* wTl = wT + l * 4224;
        for (int idx = threadIdx.x; idx < 2048; idx += 512) {
            int k = idx >> 4, j = idx & 15;
            wTl[j * 132 + k]        = w1[idx];          // Wa
            wTl[(16 + j) * 132 + k] = w1[2048 + idx];   // Wb
        }
        for (int idx = threadIdx.x; idx < 128; idx += 512) {
            sLn[l * 256 + idx]       = lnw[l * 128 + idx];
            sLn[l * 256 + 128 + idx] = lnb[l * 128 + idx];
        }
    }
    __syncthreads();

    int warp = threadIdx.x >> 5, lane = threadIdx.x & 31;
    float* rb = rowbuf + warp * (8 * 132);
    int j = lane & 15;
    int h = lane >> 4;                         // k-half
    int sts_off = 4 * lane + (h ? 4 : 0);
    int lds_off = h ? 68 : 0;
    float* dstbase = (h == 0) ? g_p : g_q;

    int stride = gridDim.x * LNW * 8;
    for (int row0 = (blockIdx.x * LNW + warp) * 8; row0 < n; row0 += stride) {
        int nr = n - row0; if (nr > 8) nr = 8;

        float4 v[8];
        #pragma unroll
        for (int r = 0; r < 8; ++r) {
            int rr = (r < nr) ? r : (nr - 1);
            v[r] = reinterpret_cast<const float4*>(s_in)[(size_t)(row0 + rr) * 32 + lane];
        }

        for (int l = 0; l < L; ++l) {
            const float4* lnp = reinterpret_cast<const float4*>(sLn + l * 256);
            float4 wv = lnp[lane], bv = lnp[32 + lane];

            float s1[8], s2[8];
            #pragma unroll
            for (int r = 0; r < 8; ++r) {
                s1[r] = (v[r].x + v[r].y) + (v[r].z + v[r].w);
                s2[r] = fmaf(v[r].x, v[r].x,
                        fmaf(v[r].y, v[r].y,
                        fmaf(v[r].z, v[r].z, v[r].w * v[r].w)));
            }
            #pragma unroll
            for (int o = 16; o; o >>= 1) {
                #pragma unroll
                for (int r = 0; r < 8; ++r) {
                    s1[r] += __shfl_xor_sync(0xffffffffu, s1[r], o);
                    s2[r] += __shfl_xor_sync(0xffffffffu, s2[r], o);
                }
            }
            #pragma unroll
            for (int r = 0; r < 8; ++r) {
                float mu = s1[r] * 0.0078125f;
                float rstd = rsqrtf(fmaf(s2[r], 0.0078125f, -mu * mu) + 1e-5f);
                v[r].x = (v[r].x - mu) * rstd * wv.x + bv.x;
                v[r].y = (v[r].y - mu) * rstd * wv.y + bv.y;
                v[r].z = (v[r].z - mu) * rstd * wv.z + bv.z;
                v[r].w = (v[r].w - mu) * rstd * wv.w + bv.w;
                *reinterpret_cast<float4*>(rb + r * 132 + sts_off) = v[r];
            }
            __syncwarp();

            const float* wbase = wT + l * 4224;
            const ulonglong2* wp =
                reinterpret_cast<const ulonglong2*>(wbase + j * 132 + h * 64);
            const ulonglong2* wq =
                reinterpret_cast<const ulonglong2*>(wbase + (16 + j) * 132 + h * 64);

            unsigned long long ap[8] = {0,0,0,0,0,0,0,0};
            unsigned long long aq[8] = {0,0,0,0,0,0,0,0};
            #pragma unroll
            for (int c = 0; c < 16; ++c) {
                ulonglong2 wpv = wp[c];
                ulonglong2 wqv = wq[c];
                #pragma unroll
                for (int r = 0; r < 8; ++r) {
                    ulonglong2 rv = *reinterpret_cast<const ulonglong2*>(
                        rb + r * 132 + lds_off + c * 4);
                    ap[r] = fma2(rv.x, wpv.x, ap[r]);
                    ap[r] = fma2(rv.y, wpv.y, ap[r]);
                    aq[r] = fma2(rv.x, wqv.x, aq[r]);
                    aq[r] = fma2(rv.y, wqv.y, aq[r]);
                }
            }
            #pragma unroll
            for (int r = 0; r < 8; ++r) {
                unsigned long long op = __shfl_xor_sync(0xffffffffu, ap[r], 16);
                unsigned long long oq = __shfl_xor_sync(0xffffffffu, aq[r], 16);
                unsigned long long tot = (h == 0) ? add2(ap[r], op) : add2(aq[r], oq);
                float2 a = up2(tot);
                if (r < nr)
                    dstbase[((size_t)l * N_MAX + (row0 + r)) * 16 + j] = a.x + a.y;
            }
            __syncwarp();
        }

        #pragma unroll
        for (int r = 0; r < 8; ++r)
            if (r < nr)
                reinterpret_cast<float4*>(s_out)[(size_t)(row0 + r) * 32 + lane] = v[r];
    }
}

// ---- shared edge-MLP body: h (with p+q+b1 already in) -> output ea regs ----
__device__ __forceinline__ void edge_mlp(
    unsigned long long h[8], const float ea[16], float ea_out[16], int layer)
{
    #pragma unroll
    for (int k = 0; k < 16; ++k) {
        unsigned long long ek = pk2(ea[k]);
        ulonglong2 w0 = cWC[layer][k*4+0], w1 = cWC[layer][k*4+1];
        ulonglong2 w2v = cWC[layer][k*4+2], w3 = cWC[layer][k*4+3];
        h[0] = fma2(ek, w0.x,  h[0]);  h[1] = fma2(ek, w0.y,  h[1]);
        h[2] = fma2(ek, w1.x,  h[2]);  h[3] = fma2(ek, w1.y,  h[3]);
        h[4] = fma2(ek, w2v.x, h[4]);  h[5] = fma2(ek, w2v.y, h[5]);
        h[6] = fma2(ek, w3.x,  h[6]);  h[7] = fma2(ek, w3.y,  h[7]);
    }
    float z[16];
    #pragma unroll
    for (int i = 0; i < 8; ++i) {
        float2 hv = up2(h[i]);
        z[2*i]   = __fdividef(hv.x, 1.0f + __expf(-hv.x));
        z[2*i+1] = __fdividef(hv.y, 1.0f + __expf(-hv.y));
    }
    unsigned long long o[8];
    #pragma unroll
    for (int i = 0; i < 8; ++i) o[i] = cB2[layer][i];
    #pragma unroll
    for (int k = 0; k < 16; ++k) {
        unsigned long long zk = pk2(z[k]);
        ulonglong2 w0 = cW2[layer][k*4+0], w1 = cW2[layer][k*4+1];
        ulonglong2 w2v = cW2[layer][k*4+2], w3 = cW2[layer][k*4+3];
        o[0] = fma2(zk, w0.x,  o[0]);  o[1] = fma2(zk, w0.y,  o[1]);
        o[2] = fma2(zk, w1.x,  o[2]);  o[3] = fma2(zk, w1.y,  o[3]);
        o[4] = fma2(zk, w2v.x, o[4]);  o[5] = fma2(zk, w2v.y, o[5]);
        o[6] = fma2(zk, w3.x,  o[6]);  o[7] = fma2(zk, w3.y,  o[7]);
    }
    #pragma unroll
    for (int i = 0; i < 8; ++i) {
        float2 t = up2(o[i]);
        ea_out[2*i] = t.x; ea_out[2*i+1] = t.y;
    }
}

// ---------------------------------------------------------------------------
// TWO layers fused, one thread per edge. BOTH layers' p/q gathers are issued
// upfront (indices known), so layer-(l0+1) gather latency hides behind the
// layer-l0 MLP compute. Halves ea stream + index traffic vs per-layer.
// ---------------------------------------------------------------------------
__global__ __launch_bounds__(256) void edge2_kernel(
    const int* __restrict__ src, const int* __restrict__ dst,
    const float* __restrict__ ea_in, float* __restrict__ ea_out,
    int l0, int e_total)
{
    int e = blockIdx.x * 256 + threadIdx.x;
    if (e >= e_total) return;
    int l1 = l0 + 1;

    int si = src[e], di = dst[e];
    const ulonglong2* P0 =
        reinterpret_cast<const ulonglong2*>(g_p + ((size_t)l0 * N_MAX + si) * 16);
    const ulonglong2* Q0 =
        reinterpret_cast<const ulonglong2*>(g_q + ((size_t)l0 * N_MAX + di) * 16);
    const ulonglong2* P1 =
        reinterpret_cast<const ulonglong2*>(g_p + ((size_t)l1 * N_MAX + si) * 16);
    const ulonglong2* Q1 =
        reinterpret_cast<const ulonglong2*>(g_q + ((size_t)l1 * N_MAX + di) * 16);

    // issue ALL gathers upfront
    ulonglong2 p0[4], q0[4], p1[4], q1[4];
    #pragma unroll
    for (int i = 0; i < 4; ++i) { p0[i] = P0[i]; q0[i] = Q0[i]; }
    #pragma unroll
    for (int i = 0; i < 4; ++i) { p1[i] = P1[i]; q1[i] = Q1[i]; }

    float ea[16];
    {
        const float4* EA = reinterpret_cast<const float4*>(ea_in + (size_t)e * 16);
        #pragma unroll
        for (int c = 0; c < 4; ++c) {
            float4 t = EA[c];
            ea[4*c] = t.x; ea[4*c+1] = t.y; ea[4*c+2] = t.z; ea[4*c+3] = t.w;
        }
    }

    // layer l0
    unsigned long long h[8];
    #pragma unroll
    for (int i = 0; i < 4; ++i) {
        h[2*i+0] = add2(add2(p0[i].x, q0[i].x), cB1[l0][2*i+0]);
        h[2*i+1] = add2(add2(p0[i].y, q0[i].y), cB1[l0][2*i+1]);
    }
    float ea1[16];
    edge_mlp(h, ea, ea1, l0);

    // layer l0+1 (gathers already in registers)
    #pragma unroll
    for (int i = 0; i < 4; ++i) {
        h[2*i+0] = add2(add2(p1[i].x, q1[i].x), cB1[l1][2*i+0]);
        h[2*i+1] = add2(add2(p1[i].y, q1[i].y), cB1[l1][2*i+1]);
    }
    float ea2[16];
    edge_mlp(h, ea1, ea2, l1);

    float4* OUT = reinterpret_cast<float4*>(ea_out + (size_t)e * 16);
    #pragma unroll
    for (int c = 0; c < 4; ++c)
        OUT[c] = make_float4(ea2[4*c], ea2[4*c+1], ea2[4*c+2], ea2[4*c+3]);
}

// single-layer edge kernel (tail layer) — R9 proven shape
__global__ __launch_bounds__(256) void edge_kernel(
    const int* __restrict__ src, const int* __restrict__ dst,
    const float* __restrict__ ea_in, float* __restrict__ ea_out,
    int layer, int e_total)
{
    int e = blockIdx.x * 256 + threadIdx.x;
    if (e >= e_total) return;

    int si = src[e], di = dst[e];
    const ulonglong2* P =
        reinterpret_cast<const ulonglong2*>(g_p + ((size_t)layer * N_MAX + si) * 16);
    const ulonglong2* Q =
        reinterpret_cast<const ulonglong2*>(g_q + ((size_t)layer * N_MAX + di) * 16);

    unsigned long long h[8];
    #pragma unroll
    for (int i = 0; i < 4; ++i) {
        ulonglong2 pv = P[i], qv = Q[i];
        h[2*i+0] = add2(add2(pv.x, qv.x), cB1[layer][2*i+0]);
        h[2*i+1] = add2(add2(pv.y, qv.y), cB1[layer][2*i+1]);
    }

    float ea[16];
    {
        const float4* EA = reinterpret_cast<const float4*>(ea_in + (size_t)e * 16);
        #pragma unroll
        for (int c = 0; c < 4; ++c) {
            float4 t = EA[c];
            ea[4*c] = t.x; ea[4*c+1] = t.y; ea[4*c+2] = t.z; ea[4*c+3] = t.w;
        }
    }
    float eo[16];
    edge_mlp(h, ea, eo, layer);

    float4* OUT = reinterpret_cast<float4*>(ea_out + (size_t)e * 16);
    #pragma unroll
    for (int c = 0; c < 4; ++c)
        OUT[c] = make_float4(eo[4*c], eo[4*c+1], eo[4*c+2], eo[4*c+3]);
}

extern "C" void kernel_launch(void* const* d_in, const int* in_sizes, int n_in,
                              void* d_out, int out_size)
{
    const float* s0   = (const float*)d_in[0];       // [N,128]
    const int*   ei   = (const int*)d_in[1];         // [2,E] int32
    const float* ea0  = (const float*)d_in[2];       // [E,16]
    const float* lnw  = (const float*)d_in[4];       // [L,128]
    const float* lnb  = (const float*)d_in[5];       // [L,128]
    const float* eW1  = (const float*)d_in[6];       // [L,272,16]
    const float* eb1  = (const float*)d_in[7];       // [L,16]
    const float* eW2  = (const float*)d_in[8];       // [L,16,16]
    const float* eb2  = (const float*)d_in[9];       // [L,16]
    // batch / nW1 / nb1 / nW2 / nb2 are dead in the reference dataflow

    int n = in_sizes[0] / D_;
    int e = in_sizes[2] / ED_;
    int L = in_sizes[4] / D_;

    float* out    = (float*)d_out;
    float* s_buf  = out;                      // final s
    float* ea_buf = out + (size_t)n * D_;     // final edge_attr

    const int* src = ei;
    const int* dst = ei + e;

    // stage edge-MLP weights into constant memory (capturable D2D copies)
    void *pWC, *pW2, *pB1, *pB2;
    cudaGetSymbolAddress(&pWC, cWC);
    cudaGetSymbolAddress(&pW2, cW2);
    cudaGetSymbolAddress(&pB1, cB1);
    cudaGetSymbolAddress(&pB2, cB2);
    cudaMemcpy2DAsync(pWC, 1024, eW1 + 256 * 16, 272 * 16 * 4, 1024, L,
                      cudaMemcpyDeviceToDevice);
    cudaMemcpyAsync(pW2, eW2, (size_t)L * 256 * 4, cudaMemcpyDeviceToDevice);
    cudaMemcpyAsync(pB1, eb1, (size_t)L * 16 * 4, cudaMemcpyDeviceToDevice);
    cudaMemcpyAsync(pB2, eb2, (size_t)L * 16 * 4, cudaMemcpyDeviceToDevice);

    size_t shmem = (size_t)(L_MAX * 4224 + L_MAX * 256 + LNW * 8 * 132) * 4;
    cudaFuncSetAttribute(ln_all_kernel,
                         cudaFuncAttributeMaxDynamicSharedMemorySize, (int)shmem);

    ln_all_kernel<<<148, 512, shmem>>>(s0, s_buf, lnw, lnb, eW1, n, L);

    int edge_blocks = (e + 255) / 256;
    int l = 0;
    while (l + 1 < L) {
        edge2_kernel<<<edge_blocks, 256>>>(
            src, dst, (l == 0) ? ea0 : ea_buf, ea_buf, l, e);
        l += 2;
    }
    if (l < L)
        edge_kernel<<<edge_blocks, 256>>>(
            src, dst, (l == 0) ? ea0 : ea_buf, ea_buf, l, e);
}

// round 13
// speedup vs baseline: 2.3793x; 2.3793x over previous
#include <cuda_runtime.h>
#include <cuda_fp16.h>

#define D_    128
#define ED_   16
#define N_MAX 100000
#define L_MAX 5

// per-layer per-node projections in FP16, layout [layer][node][16] (32B rows)
__device__ __align__(128) __half g_p[(size_t)L_MAX * N_MAX * ED_];
__device__ __align__(128) __half g_q[(size_t)L_MAX * N_MAX * ED_];

// edge-MLP weights packed as float pairs for fma.rn.f32x2
__constant__ __align__(16) ulonglong2 cWC[L_MAX][64];
__constant__ __align__(16) ulonglong2 cW2[L_MAX][64];
__constant__ __align__(16) unsigned long long cB1[L_MAX][8];
__constant__ __align__(16) unsigned long long cB2[L_MAX][8];

// ---- f32x2 packed helpers ----
__device__ __forceinline__ unsigned long long pk2(float a) {
    unsigned long long r; asm("mov.b64 %0, {%1, %1};" : "=l"(r) : "f"(a)); return r;
}
__device__ __forceinline__ unsigned long long pack2(float a, float b) {
    unsigned long long r; asm("mov.b64 %0, {%1, %2};" : "=l"(r) : "f"(a), "f"(b)); return r;
}
__device__ __forceinline__ float2 up2(unsigned long long v) {
    float2 r; asm("mov.b64 {%0, %1}, %2;" : "=f"(r.x), "=f"(r.y) : "l"(v)); return r;
}
__device__ __forceinline__ unsigned long long fma2(unsigned long long a,
                                                   unsigned long long b,
                                                   unsigned long long c) {
    unsigned long long d;
    asm("fma.rn.f32x2 %0, %1, %2, %3;" : "=l"(d) : "l"(a), "l"(b), "l"(c));
    return d;
}
__device__ __forceinline__ unsigned long long add2(unsigned long long a,
                                                   unsigned long long b) {
    unsigned long long d;
    asm("add.rn.f32x2 %0, %1, %2;" : "=l"(d) : "l"(a), "l"(b));
    return d;
}
// half2 (as uint32) pair -> p+q+bias in packed f32x2
__device__ __forceinline__ unsigned long long cvt_pq(unsigned int ph,
                                                     unsigned int qh,
                                                     unsigned long long b) {
    float2 pf = __half22float2(*reinterpret_cast<__half2*>(&ph));
    float2 qf = __half22float2(*reinterpret_cast<__half2*>(&qh));
    return add2(pack2(pf.x + qf.x, pf.y + qf.y), b);
}

// ---------------------------------------------------------------------------
// All L layers of LayerNorm + both 128->16 projections. 8 rows per warp,
// rows live in registers across layers. Split-K projection (R11 proven).
// Outputs p/q as FP16.
// ---------------------------------------------------------------------------
#define LNW 16   // warps per block
__global__ __launch_bounds__(512) void ln_all_kernel(
    const float* __restrict__ s_in, float* __restrict__ s_out,
    const float* __restrict__ lnw, const float* __restrict__ lnb,
    const float* __restrict__ eW1 /* [L,272,16] */, int n, int L)
{
    extern __shared__ __align__(16) float sm[];
    float* wT     = sm;                       // [5][32*132] transposed Wa|Wb
    float* sLn    = wT + L_MAX * 4224;        // [5][256] lnw|lnb
    float* rowbuf = sLn + L_MAX * 256;        // [LNW warps][8*132]

    for (int l = 0; l < L; ++l) {
        const float* w1 = eW1 + (size_t)l * 272 * 16;
        float* wTl = wT + l * 4224;
        for (int idx = threadIdx.x; idx < 2048; idx += 512) {
            int k = idx >> 4, j = idx & 15;
            wTl[j * 132 + k]        = w1[idx];          // Wa
            wTl[(16 + j) * 132 + k] = w1[2048 + idx];   // Wb
        }
        for (int idx = threadIdx.x; idx < 128; idx += 512) {
            sLn[l * 256 + idx]       = lnw[l * 128 + idx];
            sLn[l * 256 + 128 + idx] = lnb[l * 128 + idx];
        }
    }
    __syncthreads();

    int warp = threadIdx.x >> 5, lane = threadIdx.x & 31;
    float* rb = rowbuf + warp * (8 * 132);
    int j = lane & 15;
    int h = lane >> 4;                         // k-half
    int sts_off = 4 * lane + (h ? 4 : 0);
    int lds_off = h ? 68 : 0;
    __half* dstbase = (h == 0) ? g_p : g_q;

    int stride = gridDim.x * LNW * 8;
    for (int row0 = (blockIdx.x * LNW + warp) * 8; row0 < n; row0 += stride) {
        int nr = n - row0; if (nr > 8) nr = 8;

        float4 v[8];
        #pragma unroll
        for (int r = 0; r < 8; ++r) {
            int rr = (r < nr) ? r : (nr - 1);
            v[r] = reinterpret_cast<const float4*>(s_in)[(size_t)(row0 + rr) * 32 + lane];
        }

        for (int l = 0; l < L; ++l) {
            const float4* lnp = reinterpret_cast<const float4*>(sLn + l * 256);
            float4 wv = lnp[lane], bv = lnp[32 + lane];

            float s1[8], s2[8];
            #pragma unroll
            for (int r = 0; r < 8; ++r) {
                s1[r] = (v[r].x + v[r].y) + (v[r].z + v[r].w);
                s2[r] = fmaf(v[r].x, v[r].x,
                        fmaf(v[r].y, v[r].y,
                        fmaf(v[r].z, v[r].z, v[r].w * v[r].w)));
            }
            #pragma unroll
            for (int o = 16; o; o >>= 1) {
                #pragma unroll
                for (int r = 0; r < 8; ++r) {
                    s1[r] += __shfl_xor_sync(0xffffffffu, s1[r], o);
                    s2[r] += __shfl_xor_sync(0xffffffffu, s2[r], o);
                }
            }
            #pragma unroll
            for (int r = 0; r < 8; ++r) {
                float mu = s1[r] * 0.0078125f;
                float rstd = rsqrtf(fmaf(s2[r], 0.0078125f, -mu * mu) + 1e-5f);
                v[r].x = (v[r].x - mu) * rstd * wv.x + bv.x;
                v[r].y = (v[r].y - mu) * rstd * wv.y + bv.y;
                v[r].z = (v[r].z - mu) * rstd * wv.z + bv.z;
                v[r].w = (v[r].w - mu) * rstd * wv.w + bv.w;
                *reinterpret_cast<float4*>(rb + r * 132 + sts_off) = v[r];
            }
            __syncwarp();

            const float* wbase = wT + l * 4224;
            const ulonglong2* wp =
                reinterpret_cast<const ulonglong2*>(wbase + j * 132 + h * 64);
            const ulonglong2* wq =
                reinterpret_cast<const ulonglong2*>(wbase + (16 + j) * 132 + h * 64);

            unsigned long long ap[8] = {0,0,0,0,0,0,0,0};
            unsigned long long aq[8] = {0,0,0,0,0,0,0,0};
            #pragma unroll
            for (int c = 0; c < 16; ++c) {
                ulonglong2 wpv = wp[c];
                ulonglong2 wqv = wq[c];
                #pragma unroll
                for (int r = 0; r < 8; ++r) {
                    ulonglong2 rv = *reinterpret_cast<const ulonglong2*>(
                        rb + r * 132 + lds_off + c * 4);
                    ap[r] = fma2(rv.x, wpv.x, ap[r]);
                    ap[r] = fma2(rv.y, wpv.y, ap[r]);
                    aq[r] = fma2(rv.x, wqv.x, aq[r]);
                    aq[r] = fma2(rv.y, wqv.y, aq[r]);
                }
            }
            #pragma unroll
            for (int r = 0; r < 8; ++r) {
                unsigned long long op = __shfl_xor_sync(0xffffffffu, ap[r], 16);
                unsigned long long oq = __shfl_xor_sync(0xffffffffu, aq[r], 16);
                unsigned long long tot = (h == 0) ? add2(ap[r], op) : add2(aq[r], oq);
                float2 a = up2(tot);
                if (r < nr)
                    dstbase[((size_t)l * N_MAX + (row0 + r)) * 16 + j] =
                        __float2half(a.x + a.y);
            }
            __syncwarp();
        }

        #pragma unroll
        for (int r = 0; r < 8; ++r)
            if (r < nr)
                reinterpret_cast<float4*>(s_out)[(size_t)(row0 + r) * 32 + lane] = v[r];
    }
}

// ---------------------------------------------------------------------------
// One thread per edge, one layer per launch (R9/R11 proven-best shape).
// p/q gathers are FP16 (32B rows): 4 LDG.128 per edge instead of 8 -> half
// the gather wavefronts and half the L2 gather bytes. MLP fully inlined.
// ---------------------------------------------------------------------------
__global__ __launch_bounds__(256) void edge_kernel(
    const int* __restrict__ src, const int* __restrict__ dst,
    const float* __restrict__ ea_in, float* __restrict__ ea_out,
    int layer, int e_total)
{
    int e = blockIdx.x * 256 + threadIdx.x;
    if (e >= e_total) return;

    int si = src[e], di = dst[e];
    const uint4* P = reinterpret_cast<const uint4*>(
        g_p + ((size_t)layer * N_MAX + si) * 16);
    const uint4* Q = reinterpret_cast<const uint4*>(
        g_q + ((size_t)layer * N_MAX + di) * 16);

    uint4 pa = P[0], pb = P[1];
    uint4 qa = Q[0], qb = Q[1];

    unsigned long long h[8];
    h[0] = cvt_pq(pa.x, qa.x, cB1[layer][0]);
    h[1] = cvt_pq(pa.y, qa.y, cB1[layer][1]);
    h[2] = cvt_pq(pa.z, qa.z, cB1[layer][2]);
    h[3] = cvt_pq(pa.w, qa.w, cB1[layer][3]);
    h[4] = cvt_pq(pb.x, qb.x, cB1[layer][4]);
    h[5] = cvt_pq(pb.y, qb.y, cB1[layer][5]);
    h[6] = cvt_pq(pb.z, qb.z, cB1[layer][6]);
    h[7] = cvt_pq(pb.w, qb.w, cB1[layer][7]);

    const float4* EA = reinterpret_cast<const float4*>(ea_in + (size_t)e * 16);
    #pragma unroll
    for (int c = 0; c < 4; ++c) {
        float4 ev = EA[c];
        float es[4] = {ev.x, ev.y, ev.z, ev.w};
        #pragma unroll
        for (int kk = 0; kk < 4; ++kk) {
            int k = c * 4 + kk;
            unsigned long long ek = pk2(es[kk]);
            ulonglong2 w0 = cWC[layer][k*4+0], w1 = cWC[layer][k*4+1];
            ulonglong2 w2v = cWC[layer][k*4+2], w3 = cWC[layer][k*4+3];
            h[0] = fma2(ek, w0.x,  h[0]);  h[1] = fma2(ek, w0.y,  h[1]);
            h[2] = fma2(ek, w1.x,  h[2]);  h[3] = fma2(ek, w1.y,  h[3]);
            h[4] = fma2(ek, w2v.x, h[4]);  h[5] = fma2(ek, w2v.y, h[5]);
            h[6] = fma2(ek, w3.x,  h[6]);  h[7] = fma2(ek, w3.y,  h[7]);
        }
    }

    float z[16];
    #pragma unroll
    for (int i = 0; i < 8; ++i) {
        float2 hv = up2(h[i]);
        z[2*i]   = __fdividef(hv.x, 1.0f + __expf(-hv.x));   // silu
        z[2*i+1] = __fdividef(hv.y, 1.0f + __expf(-hv.y));
    }

    unsigned long long o[8];
    #pragma unroll
    for (int i = 0; i < 8; ++i) o[i] = cB2[layer][i];
    #pragma unroll
    for (int k = 0; k < 16; ++k) {
        unsigned long long zk = pk2(z[k]);
        ulonglong2 w0 = cW2[layer][k*4+0], w1 = cW2[layer][k*4+1];
        ulonglong2 w2v = cW2[layer][k*4+2], w3 = cW2[layer][k*4+3];
        o[0] = fma2(zk, w0.x,  o[0]);  o[1] = fma2(zk, w0.y,  o[1]);
        o[2] = fma2(zk, w1.x,  o[2]);  o[3] = fma2(zk, w1.y,  o[3]);
        o[4] = fma2(zk, w2v.x, o[4]);  o[5] = fma2(zk, w2v.y, o[5]);
        o[6] = fma2(zk, w3.x,  o[6]);  o[7] = fma2(zk, w3.y,  o[7]);
    }

    ulonglong2* OUT = reinterpret_cast<ulonglong2*>(ea_out + (size_t)e * 16);
    #pragma unroll
    for (int i = 0; i < 4; ++i)
        OUT[i] = make_ulonglong2(o[2*i], o[2*i+1]);
}

extern "C" void kernel_launch(void* const* d_in, const int* in_sizes, int n_in,
                              void* d_out, int out_size)
{
    const float* s0   = (const float*)d_in[0];       // [N,128]
    const int*   ei   = (const int*)d_in[1];         // [2,E] int32
    const float* ea0  = (const float*)d_in[2];       // [E,16]
    const float* lnw  = (const float*)d_in[4];       // [L,128]
    const float* lnb  = (const float*)d_in[5];       // [L,128]
    const float* eW1  = (const float*)d_in[6];       // [L,272,16]
    const float* eb1  = (const float*)d_in[7];       // [L,16]
    const float* eW2  = (const float*)d_in[8];       // [L,16,16]
    const float* eb2  = (const float*)d_in[9];       // [L,16]
    // batch / nW1 / nb1 / nW2 / nb2 are dead in the reference dataflow

    int n = in_sizes[0] / D_;
    int e = in_sizes[2] / ED_;
    int L = in_sizes[4] / D_;

    float* out    = (float*)d_out;
    float* s_buf  = out;                      // final s
    float* ea_buf = out + (size_t)n * D_;     // final edge_attr

    const int* src = ei;
    const int* dst = ei + e;

    // stage edge-MLP weights into constant memory (capturable D2D copies)
    void *pWC, *pW2, *pB1, *pB2;
    cudaGetSymbolAddress(&pWC, cWC);
    cudaGetSymbolAddress(&pW2, cW2);
    cudaGetSymbolAddress(&pB1, cB1);
    cudaGetSymbolAddress(&pB2, cB2);
    cudaMemcpy2DAsync(pWC, 1024, eW1 + 256 * 16, 272 * 16 * 4, 1024, L,
                      cudaMemcpyDeviceToDevice);
    cudaMemcpyAsync(pW2, eW2, (size_t)L * 256 * 4, cudaMemcpyDeviceToDevice);
    cudaMemcpyAsync(pB1, eb1, (size_t)L * 16 * 4, cudaMemcpyDeviceToDevice);
    cudaMemcpyAsync(pB2, eb2, (size_t)L * 16 * 4, cudaMemcpyDeviceToDevice);

    size_t shmem = (size_t)(L_MAX * 4224 + L_MAX * 256 + LNW * 8 * 132) * 4;
    cudaFuncSetAttribute(ln_all_kernel,
                         cudaFuncAttributeMaxDynamicSharedMemorySize, (int)shmem);

    ln_all_kernel<<<148, 512, shmem>>>(s0, s_buf, lnw, lnb, eW1, n, L);

    int edge_blocks = (e + 255) / 256;
    for (int i = 0; i < L; ++i)
        edge_kernel<<<edge_blocks, 256>>>(
            src, dst,
            (i == 0) ? ea0 : ea_buf, ea_buf,
            i, e);
}

// round 14
// speedup vs baseline: 2.3795x; 1.0001x over previous
#include <cuda_runtime.h>
#include <cuda_fp16.h>

#define D_    128
#define ED_   16
#define N_MAX 100000
#define L_MAX 5

// per-layer per-node projections in FP16, layout [layer][node][16] (32B rows)
__device__ __align__(128) __half g_p[(size_t)L_MAX * N_MAX * ED_];
__device__ __align__(128) __half g_q[(size_t)L_MAX * N_MAX * ED_];

// edge-MLP weights packed as float pairs for fma.rn.f32x2
__constant__ __align__(16) ulonglong2 cWC[L_MAX][64];
__constant__ __align__(16) ulonglong2 cW2[L_MAX][64];
__constant__ __align__(16) unsigned long long cB1[L_MAX][8];
__constant__ __align__(16) unsigned long long cB2[L_MAX][8];

// ---- f32x2 packed helpers ----
__device__ __forceinline__ unsigned long long pk2(float a) {
    unsigned long long r; asm("mov.b64 %0, {%1, %1};" : "=l"(r) : "f"(a)); return r;
}
__device__ __forceinline__ unsigned long long pack2(float a, float b) {
    unsigned long long r; asm("mov.b64 %0, {%1, %2};" : "=l"(r) : "f"(a), "f"(b)); return r;
}
__device__ __forceinline__ float2 up2(unsigned long long v) {
    float2 r; asm("mov.b64 {%0, %1}, %2;" : "=f"(r.x), "=f"(r.y) : "l"(v)); return r;
}
__device__ __forceinline__ unsigned long long fma2(unsigned long long a,
                                                   unsigned long long b,
                                                   unsigned long long c) {
    unsigned long long d;
    asm("fma.rn.f32x2 %0, %1, %2, %3;" : "=l"(d) : "l"(a), "l"(b), "l"(c));
    return d;
}
__device__ __forceinline__ unsigned long long add2(unsigned long long a,
                                                   unsigned long long b) {
    unsigned long long d;
    asm("add.rn.f32x2 %0, %1, %2;" : "=l"(d) : "l"(a), "l"(b));
    return d;
}
// half2 (as uint32) pair -> p+q+bias in packed f32x2
__device__ __forceinline__ unsigned long long cvt_pq(unsigned int ph,
                                                     unsigned int qh,
                                                     unsigned long long b) {
    float2 pf = __half22float2(*reinterpret_cast<__half2*>(&ph));
    float2 qf = __half22float2(*reinterpret_cast<__half2*>(&qh));
    return add2(pack2(pf.x + qf.x, pf.y + qf.y), b);
}

// ---------------------------------------------------------------------------
// ONE layer of LayerNorm + both 128->16 projections (split-K, R11/R13 body).
// 8 rows per warp; per-layer so the LN chain can run on a forked stream and
// overlap the edge chain. s is L2-resident so the re-read per layer is cheap.
// ---------------------------------------------------------------------------
#define LNW 16   // warps per block
__global__ __launch_bounds__(512) void ln_layer_kernel(
    const float* __restrict__ s_in, float* __restrict__ s_out,
    const float* __restrict__ lnw, const float* __restrict__ lnb,
    const float* __restrict__ eW1 /* [L,272,16] */, int layer, int n)
{
    extern __shared__ __align__(16) float sm[];
    float* wT     = sm;                       // [32*132] transposed Wa|Wb
    float* sLn    = wT + 4224;                // [256] lnw|lnb
    float* rowbuf = sLn + 256;                // [LNW warps][8*132]

    {
        const float* w1 = eW1 + (size_t)layer * 272 * 16;
        for (int idx = threadIdx.x; idx < 2048; idx += 512) {
            int k = idx >> 4, j = idx & 15;
            wT[j * 132 + k]        = w1[idx];          // Wa
            wT[(16 + j) * 132 + k] = w1[2048 + idx];   // Wb
        }
        for (int idx = threadIdx.x; idx < 128; idx += 512) {
            sLn[idx]       = lnw[layer * 128 + idx];
            sLn[128 + idx] = lnb[layer * 128 + idx];
        }
    }
    __syncthreads();

    int warp = threadIdx.x >> 5, lane = threadIdx.x & 31;
    float* rb = rowbuf + warp * (8 * 132);
    int j = lane & 15;
    int h = lane >> 4;                         // k-half
    int sts_off = 4 * lane + (h ? 4 : 0);
    int lds_off = h ? 68 : 0;
    __half* dstbase = (h == 0) ? g_p : g_q;

    float4 wv = reinterpret_cast<const float4*>(sLn)[lane];
    float4 bv = reinterpret_cast<const float4*>(sLn)[32 + lane];
    const ulonglong2* wp =
        reinterpret_cast<const ulonglong2*>(wT + j * 132 + h * 64);
    const ulonglong2* wq =
        reinterpret_cast<const ulonglong2*>(wT + (16 + j) * 132 + h * 64);

    int stride = gridDim.x * LNW * 8;
    for (int row0 = (blockIdx.x * LNW + warp) * 8; row0 < n; row0 += stride) {
        int nr = n - row0; if (nr > 8) nr = 8;

        float4 v[8];
        #pragma unroll
        for (int r = 0; r < 8; ++r) {
            int rr = (r < nr) ? r : (nr - 1);
            v[r] = reinterpret_cast<const float4*>(s_in)[(size_t)(row0 + rr) * 32 + lane];
        }

        float s1[8], s2[8];
        #pragma unroll
        for (int r = 0; r < 8; ++r) {
            s1[r] = (v[r].x + v[r].y) + (v[r].z + v[r].w);
            s2[r] = fmaf(v[r].x, v[r].x,
                    fmaf(v[r].y, v[r].y,
                    fmaf(v[r].z, v[r].z, v[r].w * v[r].w)));
        }
        #pragma unroll
        for (int o = 16; o; o >>= 1) {
            #pragma unroll
            for (int r = 0; r < 8; ++r) {
                s1[r] += __shfl_xor_sync(0xffffffffu, s1[r], o);
                s2[r] += __shfl_xor_sync(0xffffffffu, s2[r], o);
            }
        }
        #pragma unroll
        for (int r = 0; r < 8; ++r) {
            float mu = s1[r] * 0.0078125f;
            float rstd = rsqrtf(fmaf(s2[r], 0.0078125f, -mu * mu) + 1e-5f);
            v[r].x = (v[r].x - mu) * rstd * wv.x + bv.x;
            v[r].y = (v[r].y - mu) * rstd * wv.y + bv.y;
            v[r].z = (v[r].z - mu) * rstd * wv.z + bv.z;
            v[r].w = (v[r].w - mu) * rstd * wv.w + bv.w;
            *reinterpret_cast<float4*>(rb + r * 132 + sts_off) = v[r];
        }
        __syncwarp();

        unsigned long long ap[8] = {0,0,0,0,0,0,0,0};
        unsigned long long aq[8] = {0,0,0,0,0,0,0,0};
        #pragma unroll
        for (int c = 0; c < 16; ++c) {
            ulonglong2 wpv = wp[c];
            ulonglong2 wqv = wq[c];
            #pragma unroll
            for (int r = 0; r < 8; ++r) {
                ulonglong2 rv = *reinterpret_cast<const ulonglong2*>(
                    rb + r * 132 + lds_off + c * 4);
                ap[r] = fma2(rv.x, wpv.x, ap[r]);
                ap[r] = fma2(rv.y, wpv.y, ap[r]);
                aq[r] = fma2(rv.x, wqv.x, aq[r]);
                aq[r] = fma2(rv.y, wqv.y, aq[r]);
            }
        }
        #pragma unroll
        for (int r = 0; r < 8; ++r) {
            unsigned long long op = __shfl_xor_sync(0xffffffffu, ap[r], 16);
            unsigned long long oq = __shfl_xor_sync(0xffffffffu, aq[r], 16);
            unsigned long long tot = (h == 0) ? add2(ap[r], op) : add2(aq[r], oq);
            float2 a = up2(tot);
            if (r < nr)
                dstbase[((size_t)layer * N_MAX + (row0 + r)) * 16 + j] =
                    __float2half(a.x + a.y);
        }
        __syncwarp();

        #pragma unroll
        for (int r = 0; r < 8; ++r)
            if (r < nr)
                reinterpret_cast<float4*>(s_out)[(size_t)(row0 + r) * 32 + lane] = v[r];
    }
}

// ---------------------------------------------------------------------------
// One thread per edge, one layer per launch (R13 proven shape). FP16 p/q
// gathers, constant-port weights, fully inlined packed-f32x2 MLP.
// ---------------------------------------------------------------------------
__global__ __launch_bounds__(256) void edge_kernel(
    const int* __restrict__ src, const int* __restrict__ dst,
    const float* __restrict__ ea_in, float* __restrict__ ea_out,
    int layer, int e_total)
{
    int e = blockIdx.x * 256 + threadIdx.x;
    if (e >= e_total) return;

    int si = src[e], di = dst[e];
    const uint4* P = reinterpret_cast<const uint4*>(
        g_p + ((size_t)layer * N_MAX + si) * 16);
    const uint4* Q = reinterpret_cast<const uint4*>(
        g_q + ((size_t)layer * N_MAX + di) * 16);

    uint4 pa = P[0], pb = P[1];
    uint4 qa = Q[0], qb = Q[1];

    unsigned long long h[8];
    h[0] = cvt_pq(pa.x, qa.x, cB1[layer][0]);
    h[1] = cvt_pq(pa.y, qa.y, cB1[layer][1]);
    h[2] = cvt_pq(pa.z, qa.z, cB1[layer][2]);
    h[3] = cvt_pq(pa.w, qa.w, cB1[layer][3]);
    h[4] = cvt_pq(pb.x, qb.x, cB1[layer][4]);
    h[5] = cvt_pq(pb.y, qb.y, cB1[layer][5]);
    h[6] = cvt_pq(pb.z, qb.z, cB1[layer][6]);
    h[7] = cvt_pq(pb.w, qb.w, cB1[layer][7]);

    const float4* EA = reinterpret_cast<const float4*>(ea_in + (size_t)e * 16);
    #pragma unroll
    for (int c = 0; c < 4; ++c) {
        float4 ev = EA[c];
        float es[4] = {ev.x, ev.y, ev.z, ev.w};
        #pragma unroll
        for (int kk = 0; kk < 4; ++kk) {
            int k = c * 4 + kk;
            unsigned long long ek = pk2(es[kk]);
            ulonglong2 w0 = cWC[layer][k*4+0], w1 = cWC[layer][k*4+1];
            ulonglong2 w2v = cWC[layer][k*4+2], w3 = cWC[layer][k*4+3];
            h[0] = fma2(ek, w0.x,  h[0]);  h[1] = fma2(ek, w0.y,  h[1]);
            h[2] = fma2(ek, w1.x,  h[2]);  h[3] = fma2(ek, w1.y,  h[3]);
            h[4] = fma2(ek, w2v.x, h[4]);  h[5] = fma2(ek, w2v.y, h[5]);
            h[6] = fma2(ek, w3.x,  h[6]);  h[7] = fma2(ek, w3.y,  h[7]);
        }
    }

    float z[16];
    #pragma unroll
    for (int i = 0; i < 8; ++i) {
        float2 hv = up2(h[i]);
        z[2*i]   = __fdividef(hv.x, 1.0f + __expf(-hv.x));   // silu
        z[2*i+1] = __fdividef(hv.y, 1.0f + __expf(-hv.y));
    }

    unsigned long long o[8];
    #pragma unroll
    for (int i = 0; i < 8; ++i) o[i] = cB2[layer][i];
    #pragma unroll
    for (int k = 0; k < 16; ++k) {
        unsigned long long zk = pk2(z[k]);
        ulonglong2 w0 = cW2[layer][k*4+0], w1 = cW2[layer][k*4+1];
        ulonglong2 w2v = cW2[layer][k*4+2], w3 = cW2[layer][k*4+3];
        o[0] = fma2(zk, w0.x,  o[0]);  o[1] = fma2(zk, w0.y,  o[1]);
        o[2] = fma2(zk, w1.x,  o[2]);  o[3] = fma2(zk, w1.y,  o[3]);
        o[4] = fma2(zk, w2v.x, o[4]);  o[5] = fma2(zk, w2v.y, o[5]);
        o[6] = fma2(zk, w3.x,  o[6]);  o[7] = fma2(zk, w3.y,  o[7]);
    }

    ulonglong2* OUT = reinterpret_cast<ulonglong2*>(ea_out + (size_t)e * 16);
    #pragma unroll
    for (int i = 0; i < 4; ++i)
        OUT[i] = make_ulonglong2(o[2*i], o[2*i+1]);
}

extern "C" void kernel_launch(void* const* d_in, const int* in_sizes, int n_in,
                              void* d_out, int out_size)
{
    const float* s0   = (const float*)d_in[0];       // [N,128]
    const int*   ei   = (const int*)d_in[1];         // [2,E] int32
    const float* ea0  = (const float*)d_in[2];       // [E,16]
    const float* lnw  = (const float*)d_in[4];       // [L,128]
    const float* lnb  = (const float*)d_in[5];       // [L,128]
    const float* eW1  = (const float*)d_in[6];       // [L,272,16]
    const float* eb1  = (const float*)d_in[7];       // [L,16]
    const float* eW2  = (const float*)d_in[8];       // [L,16,16]
    const float* eb2  = (const float*)d_in[9];       // [L,16]
    // batch / nW1 / nb1 / nW2 / nb2 are dead in the reference dataflow

    int n = in_sizes[0] / D_;
    int e = in_sizes[2] / ED_;
    int L = in_sizes[4] / D_;

    float* out    = (float*)d_out;
    float* s_buf  = out;                      // final s
    float* ea_buf = out + (size_t)n * D_;     // final edge_attr

    const int* src = ei;
    const int* dst = ei + e;

    // stage edge-MLP weights into constant memory (capturable D2D copies)
    void *pWC, *pW2, *pB1, *pB2;
    cudaGetSymbolAddress(&pWC, cWC);
    cudaGetSymbolAddress(&pW2, cW2);
    cudaGetSymbolAddress(&pB1, cB1);
    cudaGetSymbolAddress(&pB2, cB2);
    cudaMemcpy2DAsync(pWC, 1024, eW1 + 256 * 16, 272 * 16 * 4, 1024, L,
                      cudaMemcpyDeviceToDevice);
    cudaMemcpyAsync(pW2, eW2, (size_t)L * 256 * 4, cudaMemcpyDeviceToDevice);
    cudaMemcpyAsync(pB1, eb1, (size_t)L * 16 * 4, cudaMemcpyDeviceToDevice);
    cudaMemcpyAsync(pB2, eb2, (size_t)L * 16 * 4, cudaMemcpyDeviceToDevice);

    size_t shmem = (size_t)(4224 + 256 + LNW * 8 * 132) * 4;
    cudaFuncSetAttribute(ln_layer_kernel,
                         cudaFuncAttributeMaxDynamicSharedMemorySize, (int)shmem);

    // fork a side stream for the LN chain (host objects only; bounded leak —
    // kernel_launch runs a handful of times, and none of this allocates
    // device memory)
    cudaStream_t s2;
    cudaStreamCreateWithFlags(&s2, cudaStreamNonBlocking);
    cudaEvent_t evFork;
    cudaEventCreateWithFlags(&evFork, cudaEventDisableTiming);
    cudaEventRecord(evFork, 0);
    cudaStreamWaitEvent(s2, evFork, 0);

    cudaEvent_t evLN[L_MAX];
    for (int l = 0; l < L; ++l) {
        ln_layer_kernel<<<148, 512, shmem, s2>>>(
            (l == 0) ? s0 : s_buf, s_buf, lnw, lnb, eW1, l, n);
        cudaEventCreateWithFlags(&evLN[l], cudaEventDisableTiming);
        cudaEventRecord(evLN[l], s2);
    }

    int edge_blocks = (e + 255) / 256;
    for (int l = 0; l < L; ++l) {
        cudaStreamWaitEvent(0, evLN[l], 0);
        edge_kernel<<<edge_blocks, 256>>>(
            src, dst,
            (l == 0) ? ea0 : ea_buf, ea_buf,
            l, e);
    }
    // main stream waited on evLN[L-1] (the last LN kernel) before edge L-1,
    // so the side-stream chain is fully joined into the captured graph.
}

// round 15
// speedup vs baseline: 2.4087x; 1.0123x over previous
#include <cuda_runtime.h>
#include <cuda_fp16.h>

#define D_    128
#define ED_   16
#define N_MAX 100000
#define L_MAX 5

// per-layer per-node projections in FP16, layout [layer][node][16] (32B rows)
__device__ __align__(128) __half g_p[(size_t)L_MAX * N_MAX * ED_];
__device__ __align__(128) __half g_q[(size_t)L_MAX * N_MAX * ED_];

// edge-MLP weights packed as float pairs for fma.rn.f32x2
__constant__ __align__(16) ulonglong2 cWC[L_MAX][64];
__constant__ __align__(16) ulonglong2 cW2[L_MAX][64];
__constant__ __align__(16) unsigned long long cB1[L_MAX][8];
__constant__ __align__(16) unsigned long long cB2[L_MAX][8];

// ---- f32x2 packed helpers ----
__device__ __forceinline__ unsigned long long pk2(float a) {
    unsigned long long r; asm("mov.b64 %0, {%1, %1};" : "=l"(r) : "f"(a)); return r;
}
__device__ __forceinline__ unsigned long long pack2(float a, float b) {
    unsigned long long r; asm("mov.b64 %0, {%1, %2};" : "=l"(r) : "f"(a), "f"(b)); return r;
}
__device__ __forceinline__ float2 up2(unsigned long long v) {
    float2 r; asm("mov.b64 {%0, %1}, %2;" : "=f"(r.x), "=f"(r.y) : "l"(v)); return r;
}
__device__ __forceinline__ unsigned long long fma2(unsigned long long a,
                                                   unsigned long long b,
                                                   unsigned long long c) {
    unsigned long long d;
    asm("fma.rn.f32x2 %0, %1, %2, %3;" : "=l"(d) : "l"(a), "l"(b), "l"(c));
    return d;
}
__device__ __forceinline__ unsigned long long add2(unsigned long long a,
                                                   unsigned long long b) {
    unsigned long long d;
    asm("add.rn.f32x2 %0, %1, %2;" : "=l"(d) : "l"(a), "l"(b));
    return d;
}
// half2 (as uint32) pair -> p+q+bias in packed f32x2
__device__ __forceinline__ unsigned long long cvt_pq(unsigned int ph,
                                                     unsigned int qh,
                                                     unsigned long long b) {
    float2 pf = __half22float2(*reinterpret_cast<__half2*>(&ph));
    float2 qf = __half22float2(*reinterpret_cast<__half2*>(&qh));
    return add2(pack2(pf.x + qf.x, pf.y + qf.y), b);
}

// Inline MLP body macro: h[8] must hold p+q+b1; EA_ARR in/out (overwritten).
// All loops fully unrolled, all indices compile-time -> registers only.
#define EDGE_MLP(LYR, EA_ARR)                                                   \
    {                                                                           \
        _Pragma("unroll")                                                       \
        for (int k = 0; k < 16; ++k) {                                          \
            unsigned long long ek = pk2(EA_ARR[k]);                             \
            ulonglong2 w0 = cWC[LYR][k*4+0], w1 = cWC[LYR][k*4+1];              \
            ulonglong2 w2v = cWC[LYR][k*4+2], w3 = cWC[LYR][k*4+3];             \
            h[0] = fma2(ek, w0.x,  h[0]);  h[1] = fma2(ek, w0.y,  h[1]);        \
            h[2] = fma2(ek, w1.x,  h[2]);  h[3] = fma2(ek, w1.y,  h[3]);        \
            h[4] = fma2(ek, w2v.x, h[4]);  h[5] = fma2(ek, w2v.y, h[5]);        \
            h[6] = fma2(ek, w3.x,  h[6]);  h[7] = fma2(ek, w3.y,  h[7]);        \
        }                                                                       \
        float z[16];                                                            \
        _Pragma("unroll")                                                       \
        for (int i = 0; i < 8; ++i) {                                           \
            float2 hv = up2(h[i]);                                              \
            z[2*i]   = __fdividef(hv.x, 1.0f + __expf(-hv.x));                  \
            z[2*i+1] = __fdividef(hv.y, 1.0f + __expf(-hv.y));                  \
        }                                                                       \
        unsigned long long o[8];                                                \
        _Pragma("unroll")                                                       \
        for (int i = 0; i < 8; ++i) o[i] = cB2[LYR][i];                         \
        _Pragma("unroll")                                                       \
        for (int k = 0; k < 16; ++k) {                                          \
            unsigned long long zk = pk2(z[k]);                                  \
            ulonglong2 w0 = cW2[LYR][k*4+0], w1 = cW2[LYR][k*4+1];              \
            ulonglong2 w2v = cW2[LYR][k*4+2], w3 = cW2[LYR][k*4+3];             \
            o[0] = fma2(zk, w0.x,  o[0]);  o[1] = fma2(zk, w0.y,  o[1]);        \
            o[2] = fma2(zk, w1.x,  o[2]);  o[3] = fma2(zk, w1.y,  o[3]);        \
            o[4] = fma2(zk, w2v.x, o[4]);  o[5] = fma2(zk, w2v.y, o[5]);        \
            o[6] = fma2(zk, w3.x,  o[6]);  o[7] = fma2(zk, w3.y,  o[7]);        \
        }                                                                       \
        _Pragma("unroll")                                                       \
        for (int i = 0; i < 8; ++i) {                                           \
            float2 t = up2(o[i]);                                               \
            EA_ARR[2*i] = t.x; EA_ARR[2*i+1] = t.y;                             \
        }                                                                       \
    }

// ---------------------------------------------------------------------------
// ONE layer of LayerNorm + both 128->16 projections (split-K). Per-layer so
// the LN chain runs on a forked stream and overlaps the edge chain.
// ---------------------------------------------------------------------------
#define LNW 16   // warps per block
__global__ __launch_bounds__(512) void ln_layer_kernel(
    const float* __restrict__ s_in, float* __restrict__ s_out,
    const float* __restrict__ lnw, const float* __restrict__ lnb,
    const float* __restrict__ eW1 /* [L,272,16] */, int layer, int n)
{
    extern __shared__ __align__(16) float sm[];
    float* wT     = sm;                       // [32*132] transposed Wa|Wb
    float* sLn    = wT + 4224;                // [256] lnw|lnb
    float* rowbuf = sLn + 256;                // [LNW warps][8*132]

    {
        const float* w1 = eW1 + (size_t)layer * 272 * 16;
        for (int idx = threadIdx.x; idx < 2048; idx += 512) {
            int k = idx >> 4, j = idx & 15;
            wT[j * 132 + k]        = w1[idx];          // Wa
            wT[(16 + j) * 132 + k] = w1[2048 + idx];   // Wb
        }
        for (int idx = threadIdx.x; idx < 128; idx += 512) {
            sLn[idx]       = lnw[layer * 128 + idx];
            sLn[128 + idx] = lnb[layer * 128 + idx];
        }
    }
    __syncthreads();

    int warp = threadIdx.x >> 5, lane = threadIdx.x & 31;
    float* rb = rowbuf + warp * (8 * 132);
    int j = lane & 15;
    int h = lane >> 4;                         // k-half
    int sts_off = 4 * lane + (h ? 4 : 0);
    int lds_off = h ? 68 : 0;
    __half* dstbase = (h == 0) ? g_p : g_q;

    float4 wv = reinterpret_cast<const float4*>(sLn)[lane];
    float4 bv = reinterpret_cast<const float4*>(sLn)[32 + lane];
    const ulonglong2* wp =
        reinterpret_cast<const ulonglong2*>(wT + j * 132 + h * 64);
    const ulonglong2* wq =
        reinterpret_cast<const ulonglong2*>(wT + (16 + j) * 132 + h * 64);

    int stride = gridDim.x * LNW * 8;
    for (int row0 = (blockIdx.x * LNW + warp) * 8; row0 < n; row0 += stride) {
        int nr = n - row0; if (nr > 8) nr = 8;

        float4 v[8];
        #pragma unroll
        for (int r = 0; r < 8; ++r) {
            int rr = (r < nr) ? r : (nr - 1);
            v[r] = reinterpret_cast<const float4*>(s_in)[(size_t)(row0 + rr) * 32 + lane];
        }

        float s1[8], s2[8];
        #pragma unroll
        for (int r = 0; r < 8; ++r) {
            s1[r] = (v[r].x + v[r].y) + (v[r].z + v[r].w);
            s2[r] = fmaf(v[r].x, v[r].x,
                    fmaf(v[r].y, v[r].y,
                    fmaf(v[r].z, v[r].z, v[r].w * v[r].w)));
        }
        #pragma unroll
        for (int o = 16; o; o >>= 1) {
            #pragma unroll
            for (int r = 0; r < 8; ++r) {
                s1[r] += __shfl_xor_sync(0xffffffffu, s1[r], o);
                s2[r] += __shfl_xor_sync(0xffffffffu, s2[r], o);
            }
        }
        #pragma unroll
        for (int r = 0; r < 8; ++r) {
            float mu = s1[r] * 0.0078125f;
            float rstd = rsqrtf(fmaf(s2[r], 0.0078125f, -mu * mu) + 1e-5f);
            v[r].x = (v[r].x - mu) * rstd * wv.x + bv.x;
            v[r].y = (v[r].y - mu) * rstd * wv.y + bv.y;
            v[r].z = (v[r].z - mu) * rstd * wv.z + bv.z;
            v[r].w = (v[r].w - mu) * rstd * wv.w + bv.w;
            *reinterpret_cast<float4*>(rb + r * 132 + sts_off) = v[r];
        }
        __syncwarp();

        unsigned long long ap[8] = {0,0,0,0,0,0,0,0};
        unsigned long long aq[8] = {0,0,0,0,0,0,0,0};
        #pragma unroll
        for (int c = 0; c < 16; ++c) {
            ulonglong2 wpv = wp[c];
            ulonglong2 wqv = wq[c];
            #pragma unroll
            for (int r = 0; r < 8; ++r) {
                ulonglong2 rv = *reinterpret_cast<const ulonglong2*>(
                    rb + r * 132 + lds_off + c * 4);
                ap[r] = fma2(rv.x, wpv.x, ap[r]);
                ap[r] = fma2(rv.y, wpv.y, ap[r]);
                aq[r] = fma2(rv.x, wqv.x, aq[r]);
                aq[r] = fma2(rv.y, wqv.y, aq[r]);
            }
        }
        #pragma unroll
        for (int r = 0; r < 8; ++r) {
            unsigned long long op = __shfl_xor_sync(0xffffffffu, ap[r], 16);
            unsigned long long oq = __shfl_xor_sync(0xffffffffu, aq[r], 16);
            unsigned long long tot = (h == 0) ? add2(ap[r], op) : add2(aq[r], oq);
            float2 a = up2(tot);
            if (r < nr)
                dstbase[((size_t)layer * N_MAX + (row0 + r)) * 16 + j] =
                    __float2half(a.x + a.y);
        }
        __syncwarp();

        #pragma unroll
        for (int r = 0; r < 8; ++r)
            if (r < nr)
                reinterpret_cast<float4*>(s_out)[(size_t)(row0 + r) * 32 + lane] = v[r];
    }
}

// ---------------------------------------------------------------------------
// TWO edge layers fused, one thread per edge, ALL inline (no array-param
// functions -> no local-mem demotion). Both layers' fp16 p/q gathers issued
// upfront; ONE ea read + ONE ea write for the pair.
// ---------------------------------------------------------------------------
__global__ __launch_bounds__(256) void edge2_kernel(
    const int* __restrict__ src, const int* __restrict__ dst,
    const float* __restrict__ ea_in, float* __restrict__ ea_out,
    int l0, int e_total)
{
    int e = blockIdx.x * 256 + threadIdx.x;
    if (e >= e_total) return;
    int l1 = l0 + 1;

    int si = src[e], di = dst[e];
    const uint4* P0 = reinterpret_cast<const uint4*>(g_p + ((size_t)l0 * N_MAX + si) * 16);
    const uint4* Q0 = reinterpret_cast<const uint4*>(g_q + ((size_t)l0 * N_MAX + di) * 16);
    const uint4* P1 = reinterpret_cast<const uint4*>(g_p + ((size_t)l1 * N_MAX + si) * 16);
    const uint4* Q1 = reinterpret_cast<const uint4*>(g_q + ((size_t)l1 * N_MAX + di) * 16);

    // issue all 8 gathers upfront; layer-1 loads complete under layer-0 math
    uint4 pa0 = P0[0], pb0 = P0[1], qa0 = Q0[0], qb0 = Q0[1];
    uint4 pa1 = P1[0], pb1 = P1[1], qa1 = Q1[0], qb1 = Q1[1];

    float ea[16];
    {
        const float4* EA = reinterpret_cast<const float4*>(ea_in + (size_t)e * 16);
        #pragma unroll
        for (int c = 0; c < 4; ++c) {
            float4 t = EA[c];
            ea[4*c] = t.x; ea[4*c+1] = t.y; ea[4*c+2] = t.z; ea[4*c+3] = t.w;
        }
    }

    // ---- layer l0 ----
    unsigned long long h[8];
    h[0] = cvt_pq(pa0.x, qa0.x, cB1[l0][0]);
    h[1] = cvt_pq(pa0.y, qa0.y, cB1[l0][1]);
    h[2] = cvt_pq(pa0.z, qa0.z, cB1[l0][2]);
    h[3] = cvt_pq(pa0.w, qa0.w, cB1[l0][3]);
    h[4] = cvt_pq(pb0.x, qb0.x, cB1[l0][4]);
    h[5] = cvt_pq(pb0.y, qb0.y, cB1[l0][5]);
    h[6] = cvt_pq(pb0.z, qb0.z, cB1[l0][6]);
    h[7] = cvt_pq(pb0.w, qb0.w, cB1[l0][7]);
    EDGE_MLP(l0, ea)

    // ---- layer l1 (gathers already in registers) ----
    h[0] = cvt_pq(pa1.x, qa1.x, cB1[l1][0]);
    h[1] = cvt_pq(pa1.y, qa1.y, cB1[l1][1]);
    h[2] = cvt_pq(pa1.z, qa1.z, cB1[l1][2]);
    h[3] = cvt_pq(pa1.w, qa1.w, cB1[l1][3]);
    h[4] = cvt_pq(pb1.x, qb1.x, cB1[l1][4]);
    h[5] = cvt_pq(pb1.y, qb1.y, cB1[l1][5]);
    h[6] = cvt_pq(pb1.z, qb1.z, cB1[l1][6]);
    h[7] = cvt_pq(pb1.w, qb1.w, cB1[l1][7]);
    EDGE_MLP(l1, ea)

    float4* OUT = reinterpret_cast<float4*>(ea_out + (size_t)e * 16);
    #pragma unroll
    for (int c = 0; c < 4; ++c)
        OUT[c] = make_float4(ea[4*c], ea[4*c+1], ea[4*c+2], ea[4*c+3]);
}

// single-layer edge kernel (tail), R13 proven shape, inline macro body
__global__ __launch_bounds__(256) void edge_kernel(
    const int* __restrict__ src, const int* __restrict__ dst,
    const float* __restrict__ ea_in, float* __restrict__ ea_out,
    int layer, int e_total)
{
    int e = blockIdx.x * 256 + threadIdx.x;
    if (e >= e_total) return;

    int si = src[e], di = dst[e];
    const uint4* P = reinterpret_cast<const uint4*>(g_p + ((size_t)layer * N_MAX + si) * 16);
    const uint4* Q = reinterpret_cast<const uint4*>(g_q + ((size_t)layer * N_MAX + di) * 16);

    uint4 pa = P[0], pb = P[1];
    uint4 qa = Q[0], qb = Q[1];

    float ea[16];
    {
        const float4* EA = reinterpret_cast<const float4*>(ea_in + (size_t)e * 16);
        #pragma unroll
        for (int c = 0; c < 4; ++c) {
            float4 t = EA[c];
            ea[4*c] = t.x; ea[4*c+1] = t.y; ea[4*c+2] = t.z; ea[4*c+3] = t.w;
        }
    }

    unsigned long long h[8];
    h[0] = cvt_pq(pa.x, qa.x, cB1[layer][0]);
    h[1] = cvt_pq(pa.y, qa.y, cB1[layer][1]);
    h[2] = cvt_pq(pa.z, qa.z, cB1[layer][2]);
    h[3] = cvt_pq(pa.w, qa.w, cB1[layer][3]);
    h[4] = cvt_pq(pb.x, qb.x, cB1[layer][4]);
    h[5] = cvt_pq(pb.y, qb.y, cB1[layer][5]);
    h[6] = cvt_pq(pb.z, qb.z, cB1[layer][6]);
    h[7] = cvt_pq(pb.w, qb.w, cB1[layer][7]);
    EDGE_MLP(layer, ea)

    float4* OUT = reinterpret_cast<float4*>(ea_out + (size_t)e * 16);
    #pragma unroll
    for (int c = 0; c < 4; ++c)
        OUT[c] = make_float4(ea[4*c], ea[4*c+1], ea[4*c+2], ea[4*c+3]);
}

extern "C" void kernel_launch(void* const* d_in, const int* in_sizes, int n_in,
                              void* d_out, int out_size)
{
    const float* s0   = (const float*)d_in[0];       // [N,128]
    const int*   ei   = (const int*)d_in[1];         // [2,E] int32
    const float* ea0  = (const float*)d_in[2];       // [E,16]
    const float* lnw  = (const float*)d_in[4];       // [L,128]
    const float* lnb  = (const float*)d_in[5];       // [L,128]
    const float* eW1  = (const float*)d_in[6];       // [L,272,16]
    const float* eb1  = (const float*)d_in[7];       // [L,16]
    const float* eW2  = (const float*)d_in[8];       // [L,16,16]
    const float* eb2  = (const float*)d_in[9];       // [L,16]
    // batch / nW1 / nb1 / nW2 / nb2 are dead in the reference dataflow

    int n = in_sizes[0] / D_;
    int e = in_sizes[2] / ED_;
    int L = in_sizes[4] / D_;

    float* out    = (float*)d_out;
    float* s_buf  = out;                      // final s
    float* ea_buf = out + (size_t)n * D_;     // final edge_attr

    const int* src = ei;
    const int* dst = ei + e;

    // stage edge-MLP weights into constant memory (capturable D2D copies)
    void *pWC, *pW2, *pB1, *pB2;
    cudaGetSymbolAddress(&pWC, cWC);
    cudaGetSymbolAddress(&pW2, cW2);
    cudaGetSymbolAddress(&pB1, cB1);
    cudaGetSymbolAddress(&pB2, cB2);
    cudaMemcpy2DAsync(pWC, 1024, eW1 + 256 * 16, 272 * 16 * 4, 1024, L,
                      cudaMemcpyDeviceToDevice);
    cudaMemcpyAsync(pW2, eW2, (size_t)L * 256 * 4, cudaMemcpyDeviceToDevice);
    cudaMemcpyAsync(pB1, eb1, (size_t)L * 16 * 4, cudaMemcpyDeviceToDevice);
    cudaMemcpyAsync(pB2, eb2, (size_t)L * 16 * 4, cudaMemcpyDeviceToDevice);

    size_t shmem = (size_t)(4224 + 256 + LNW * 8 * 132) * 4;
    cudaFuncSetAttribute(ln_layer_kernel,
                         cudaFuncAttributeMaxDynamicSharedMemorySize, (int)shmem);

    // forked stream for the LN chain (host objects only)
    cudaStream_t s2;
    cudaStreamCreateWithFlags(&s2, cudaStreamNonBlocking);
    cudaEvent_t evFork;
    cudaEventCreateWithFlags(&evFork, cudaEventDisableTiming);
    cudaEventRecord(evFork, 0);
    cudaStreamWaitEvent(s2, evFork, 0);

    cudaEvent_t evLN[L_MAX];
    for (int l = 0; l < L; ++l) {
        ln_layer_kernel<<<148, 512, shmem, s2>>>(
            (l == 0) ? s0 : s_buf, s_buf, lnw, lnb, eW1, l, n);
        cudaEventCreateWithFlags(&evLN[l], cudaEventDisableTiming);
        cudaEventRecord(evLN[l], s2);
    }

    int edge_blocks = (e + 255) / 256;
    int l = 0;
    while (l + 1 < L) {
        cudaStreamWaitEvent(0, evLN[l + 1], 0);
        edge2_kernel<<<edge_blocks, 256>>>(
            src, dst, (l == 0) ? ea0 : ea_buf, ea_buf, l, e);
        l += 2;
    }
    if (l < L) {
        cudaStreamWaitEvent(0, evLN[l], 0);
        edge_kernel<<<edge_blocks, 256>>>(
            src, dst, (l == 0) ? ea0 : ea_buf, ea_buf, l, e);
    }
}